// round 2
// baseline (speedup 1.0000x reference)
#include <cuda_runtime.h>
#include <cstdint>

#define B_   64
#define T_   2048
#define DIN  128
#define DH   256
#define WST  384   // W row stride (fan_in = 128 + 256)

// 128MB scratch for xw = x @ Wx^T + b   (sanctioned __device__ scratch)
__device__ float g_xw[33554432];   // 64*2048*256

// ---------- packed f32x2 helpers ----------
__device__ __forceinline__ unsigned long long pk2(float x, float y) {
    unsigned long long r;
    asm("mov.b64 %0, {%1,%2};" : "=l"(r) : "f"(x), "f"(y));
    return r;
}
__device__ __forceinline__ float2 up2(unsigned long long v) {
    float2 r;
    asm("mov.b64 {%0,%1}, %2;" : "=f"(r.x), "=f"(r.y) : "l"(v));
    return r;
}
__device__ __forceinline__ void fma2(unsigned long long& d,
                                     unsigned long long a,
                                     unsigned long long b) {
    asm("fma.rn.f32x2 %0, %1, %2, %3;" : "=l"(d) : "l"(a), "l"(b), "l"(d));
}

// ============================================================================
// Kernel 1: xw[m][n] = sum_k X[m][k] * W[n][k] + bias[n]
//   M = B*T = 131072, N = 256, K = 128.  BM=128, BN=64, two K-chunks of 64.
//   K-major f32x2 accumulation; W tile XOR-swizzled in smem.
// ============================================================================
__global__ __launch_bounds__(256, 1) void gemm_xw_kernel(
    const float* __restrict__ X, const float* __restrict__ W,
    const float* __restrict__ bias)
{
    __shared__ __align__(16) float  Xs[128][64];
    __shared__ __align__(16) float4 Wsv[64][16];

    const int tid = threadIdx.x;
    const int m0 = blockIdx.x * 128;
    const int n0 = blockIdx.y * 64;
    const int tx = tid & 15;
    const int ty = tid >> 4;
    const int row = ty * 8;

    unsigned long long acc[8][4];
#pragma unroll
    for (int i = 0; i < 8; i++)
#pragma unroll
        for (int j = 0; j < 4; j++) acc[i][j] = 0ULL;

    for (int kb = 0; kb < 2; kb++) {
        // load X tile [128][64]  (coalesced float4)
#pragma unroll
        for (int it = 0; it < 8; it++) {
            int v = tid + 256 * it;        // 0..2047
            int m = v >> 4;                // 16 float4 per row
            int kv = v & 15;
            float4 xv = *(const float4*)(X + (size_t)(m0 + m) * DIN + kb * 64 + kv * 4);
            *(float4*)&Xs[m][kv * 4] = xv;
        }
        // load W tile [64][64], swizzled: slot = kv ^ (n&7)
#pragma unroll
        for (int it = 0; it < 4; it++) {
            int v = tid + 256 * it;        // 0..1023
            int n = v >> 4;
            int kv = v & 15;
            float4 wv = *(const float4*)(W + (size_t)(n0 + n) * WST + kb * 64 + kv * 4);
            Wsv[n][kv ^ (n & 7)] = wv;
        }
        __syncthreads();

#pragma unroll
        for (int k4 = 0; k4 < 16; k4++) {
            ulonglong2 bv[4];
#pragma unroll
            for (int j = 0; j < 4; j++) {
                int n = tx + 16 * j;
                bv[j] = *(const ulonglong2*)&Wsv[n][k4 ^ (n & 7)];
            }
#pragma unroll
            for (int i = 0; i < 8; i++) {
                ulonglong2 av = *(const ulonglong2*)&Xs[row + i][k4 * 4];
#pragma unroll
                for (int j = 0; j < 4; j++) {
                    fma2(acc[i][j], av.x, bv[j].x);
                    fma2(acc[i][j], av.y, bv[j].y);
                }
            }
        }
        __syncthreads();
    }

    float bb[4];
#pragma unroll
    for (int j = 0; j < 4; j++) bb[j] = bias[n0 + tx + 16 * j];
#pragma unroll
    for (int i = 0; i < 8; i++) {
#pragma unroll
        for (int j = 0; j < 4; j++) {
            float2 v = up2(acc[i][j]);
            g_xw[(size_t)(m0 + row + i) * DH + n0 + tx + 16 * j] = v.x + v.y + bb[j];
        }
    }
}

// ============================================================================
// Kernel 2: persistent recurrent scan.
//   One cluster of 2 CTAs per batch. CTA s holds Wh[:, s*128:(s+1)*128] in
//   registers (64 packed f32x2 per thread, thread j = output j). Per step:
//   partial_j = Wh[j, Ks] . h[Ks]; exchange partials via DSMEM; both CTAs
//   form full h_new[j] = tanh(partial_own + partial_peer + xw[t][j]).
// ============================================================================
__global__ void __cluster_dims__(2, 1, 1) __launch_bounds__(256, 1)
rnn_scan_kernel(const float* __restrict__ W, const float* __restrict__ h0,
                float* __restrict__ out)
{
    __shared__ __align__(16) float sh_h[DH];
    __shared__ __align__(16) float sh_part[2][DH];

    const int j = threadIdx.x;
    const int b = blockIdx.x >> 1;
    const unsigned int s = (unsigned int)(blockIdx.x & 1);
    const unsigned int peer = s ^ 1u;

    // Wh K-slice into registers: wh[m] = (Wh[j][s*128+2m], Wh[j][s*128+2m+1])
    unsigned long long wh[64];
    {
        const float4* wp = (const float4*)(W + (size_t)j * WST + DIN + s * 128);
#pragma unroll
        for (int i = 0; i < 32; i++) {
            float4 v = wp[i];
            wh[2 * i]     = pk2(v.x, v.y);
            wh[2 * i + 1] = pk2(v.z, v.w);
        }
    }

    sh_h[j] = h0[(size_t)b * DH + j];

    // remote (peer-CTA) address of the partial buffer
    unsigned int lpart, rpart;
    lpart = (unsigned int)__cvta_generic_to_shared(&sh_part[0][0]);
    asm("mapa.shared::cluster.u32 %0, %1, %2;" : "=r"(rpart) : "r"(lpart), "r"(peer));

    const float* xp = g_xw + (size_t)b * T_ * DH + j;
    float*       op = out  + (size_t)b * T_ * DH + j;
    const bool do_store = ((unsigned)(j >> 7)) == s;

    float xv = __ldg(xp);        // prefetch t=0
    __syncthreads();             // sh_h visible CTA-wide before first read

    const ulonglong2* hp = (const ulonglong2*)(sh_h + (s << 7));

#pragma unroll 1
    for (int t = 0; t < T_; t++) {
        // prefetch next step's xw early (hides DRAM/L2 latency under compute)
        float xn = 0.f;
        if (t + 1 < T_) xn = __ldg(xp + (size_t)(t + 1) * DH);

        // partial_j over this CTA's K-half: 64 packed FMAs, 4 indep chains
        unsigned long long a0 = 0ULL, a1 = 0ULL, a2 = 0ULL, a3 = 0ULL;
#pragma unroll
        for (int i = 0; i < 16; i++) {
            ulonglong2 hv0 = hp[2 * i];
            ulonglong2 hv1 = hp[2 * i + 1];
            fma2(a0, wh[4 * i + 0], hv0.x);
            fma2(a1, wh[4 * i + 1], hv0.y);
            fma2(a2, wh[4 * i + 2], hv1.x);
            fma2(a3, wh[4 * i + 3], hv1.y);
        }
        float2 f0 = up2(a0), f1 = up2(a1), f2 = up2(a2), f3 = up2(a3);
        float partial = ((f0.x + f0.y) + (f1.x + f1.y)) +
                        ((f2.x + f2.y) + (f3.x + f3.y));

        // push my partial into the PEER's buffer (double-buffered by parity)
        unsigned int pa = rpart + ((unsigned)(t & 1) << 10) + ((unsigned)j << 2);
        asm volatile("st.shared::cluster.b32 [%0], %1;"
                     :: "r"(pa), "r"(__float_as_uint(partial)) : "memory");

        // cluster barrier: release my DSMEM write, acquire peer's
        asm volatile("barrier.cluster.arrive.aligned;" ::: "memory");
        asm volatile("barrier.cluster.wait.aligned;"   ::: "memory");

        float hnew = tanhf(partial + sh_part[t & 1][j] + xv);
        if (do_store) op[(size_t)t * DH] = hnew;

        sh_h[j] = hnew;       // safe: all reads of old h happened pre-barrier
        xv = xn;
        __syncthreads();      // h_new visible CTA-wide before next step
    }
}

// ============================================================================
extern "C" void kernel_launch(void* const* d_in, const int* in_sizes, int n_in,
                              void* d_out, int out_size)
{
    const float* x    = (const float*)d_in[0];   // (64, 2048, 128)
    const float* h0   = (const float*)d_in[1];   // (64, 256)
    const float* W    = (const float*)d_in[2];   // (256, 384)
    const float* bias = (const float*)d_in[3];   // (256,)
    float* out = (float*)d_out;                  // (64, 2048, 256)

    (void)in_sizes; (void)n_in; (void)out_size;

    gemm_xw_kernel<<<dim3(1024, 4), 256>>>(x, W, bias);
    rnn_scan_kernel<<<128, 256>>>(W, h0, out);
}

// round 6
// speedup vs baseline: 1.1044x; 1.1044x over previous
#include <cuda_runtime.h>
#include <cstdint>

#define B_   64
#define T_   2048
#define DIN  128
#define DH   256
#define WST  384   // W row stride (fan_in = 128 + 256)

// 128MB scratch for xw = x @ Wx^T + b   (sanctioned __device__ scratch)
__device__ float g_xw[33554432];   // 64*2048*256

// ---------- packed f32x2 helpers ----------
__device__ __forceinline__ unsigned long long pk2(float x, float y) {
    unsigned long long r;
    asm("mov.b64 %0, {%1,%2};" : "=l"(r) : "f"(x), "f"(y));
    return r;
}
__device__ __forceinline__ float2 up2(unsigned long long v) {
    float2 r;
    asm("mov.b64 {%0,%1}, %2;" : "=f"(r.x), "=f"(r.y) : "l"(v));
    return r;
}
__device__ __forceinline__ void fma2(unsigned long long& d,
                                     unsigned long long a,
                                     unsigned long long b) {
    asm("fma.rn.f32x2 %0, %1, %2, %3;" : "=l"(d) : "l"(a), "l"(b), "l"(d));
}
__device__ __forceinline__ void add2(unsigned long long& d,
                                     unsigned long long a) {
    asm("add.rn.f32x2 %0, %1, %2;" : "=l"(d) : "l"(d), "l"(a));
}

// ============================================================================
// Kernel 1: xw[m][n] = sum_k X[m][k] * W[n][k] + bias[n]
//   M = B*T = 131072, N = 256, K = 128.  BM=128, BN=64, two K-chunks of 64.
// ============================================================================
__global__ __launch_bounds__(256, 1) void gemm_xw_kernel(
    const float* __restrict__ X, const float* __restrict__ W,
    const float* __restrict__ bias)
{
    __shared__ __align__(16) float  Xs[128][64];
    __shared__ __align__(16) float4 Wsv[64][16];

    const int tid = threadIdx.x;
    const int m0 = blockIdx.x * 128;
    const int n0 = blockIdx.y * 64;
    const int tx = tid & 15;
    const int ty = tid >> 4;
    const int row = ty * 8;

    unsigned long long acc[8][4];
#pragma unroll
    for (int i = 0; i < 8; i++)
#pragma unroll
        for (int j = 0; j < 4; j++) acc[i][j] = 0ULL;

    for (int kb = 0; kb < 2; kb++) {
#pragma unroll
        for (int it = 0; it < 8; it++) {
            int v = tid + 256 * it;
            int m = v >> 4;
            int kv = v & 15;
            float4 xv = *(const float4*)(X + (size_t)(m0 + m) * DIN + kb * 64 + kv * 4);
            *(float4*)&Xs[m][kv * 4] = xv;
        }
#pragma unroll
        for (int it = 0; it < 4; it++) {
            int v = tid + 256 * it;
            int n = v >> 4;
            int kv = v & 15;
            float4 wv = *(const float4*)(W + (size_t)(n0 + n) * WST + kb * 64 + kv * 4);
            Wsv[n][kv ^ (n & 7)] = wv;
        }
        __syncthreads();

#pragma unroll
        for (int k4 = 0; k4 < 16; k4++) {
            ulonglong2 bv[4];
#pragma unroll
            for (int j = 0; j < 4; j++) {
                int n = tx + 16 * j;
                bv[j] = *(const ulonglong2*)&Wsv[n][k4 ^ (n & 7)];
            }
#pragma unroll
            for (int i = 0; i < 8; i++) {
                ulonglong2 av = *(const ulonglong2*)&Xs[row + i][k4 * 4];
#pragma unroll
                for (int j = 0; j < 4; j++) {
                    fma2(acc[i][j], av.x, bv[j].x);
                    fma2(acc[i][j], av.y, bv[j].y);
                }
            }
        }
        __syncthreads();
    }

    float bb[4];
#pragma unroll
    for (int j = 0; j < 4; j++) bb[j] = bias[n0 + tx + 16 * j];
#pragma unroll
    for (int i = 0; i < 8; i++) {
#pragma unroll
        for (int j = 0; j < 4; j++) {
            float2 v = up2(acc[i][j]);
            g_xw[(size_t)(m0 + row + i) * DH + n0 + tx + 16 * j] = v.x + v.y + bb[j];
        }
    }
}

// ============================================================================
// Kernel 2: persistent recurrent scan — OUTPUT-split 2-CTA cluster per batch.
//   CTA s owns outputs j in [s*128, s*128+128), full K=256. Two threads per
//   output (lane halves take K in [0,128)/[128,256)), combined via
//   shfl.xor(16). Each CTA pushes only its 128 final h values to the peer via
//   st.shared::cluster, ordered by an EXPLICIT cluster-scope release arrive
//   (mbarrier.arrive.release.cluster) matched by acquire.cluster try_wait.
//   (R3 bug: default .release.cta arrive did not order the DSMEM store.)
// ============================================================================
__global__ void __cluster_dims__(2, 1, 1) __launch_bounds__(256, 1)
rnn_scan_kernel(const float* __restrict__ W, const float* __restrict__ h0,
                float* __restrict__ out)
{
    __shared__ __align__(16) float sh_h[2][DH];
    __shared__ __align__(8) unsigned long long mbar;

    const int tid  = threadIdx.x;
    const int lane = tid & 31;
    const int warp = tid >> 5;                 // 8 warps
    const int sub  = lane >> 4;                // K-half selector (0/1)
    const int jl   = warp * 16 + (lane & 15);  // output within CTA: 0..127
    const int b    = blockIdx.x >> 1;
    const unsigned int s = (unsigned int)(blockIdx.x & 1);
    const unsigned int peer = s ^ 1u;
    const int j  = (int)(s << 7) + jl;         // global output index 0..255
    const int k0 = sub << 7;                   // this thread's K offset

    // Wh[j][k0 .. k0+128) into registers: 64 packed f32x2
    unsigned long long wh[64];
    {
        const float4* wp = (const float4*)(W + (size_t)j * WST + DIN + k0);
#pragma unroll
        for (int i = 0; i < 32; i++) {
            float4 v = wp[i];
            wh[2 * i]     = pk2(v.x, v.y);
            wh[2 * i + 1] = pk2(v.z, v.w);
        }
    }

    // init h state (full 256 locally in both CTAs) + mbarrier
    if (tid < DH) sh_h[0][tid] = h0[(size_t)b * DH + tid];
    unsigned int lbar = (unsigned int)__cvta_generic_to_shared(&mbar);
    if (tid == 0) {
        asm volatile("mbarrier.init.shared.b64 [%0], %1;"
                     :: "r"(lbar), "r"(128) : "memory");
    }
    __syncthreads();
    // make mbarrier init visible cluster-wide before any peer arrival
    asm volatile("barrier.cluster.arrive.aligned;" ::: "memory");
    asm volatile("barrier.cluster.wait.aligned;"   ::: "memory");

    // peer-CTA addresses
    unsigned int rbar, rh;
    asm("mapa.shared::cluster.u32 %0, %1, %2;" : "=r"(rbar) : "r"(lbar), "r"(peer));
    unsigned int lh = (unsigned int)__cvta_generic_to_shared(&sh_h[0][0]);
    asm("mapa.shared::cluster.u32 %0, %1, %2;" : "=r"(rh) : "r"(lh), "r"(peer));

    const float* xp = g_xw + (size_t)b * T_ * DH + j;
    float*       op = out  + (size_t)b * T_ * DH + j;

    float xv = __ldg(xp);   // prefetch t=0

#pragma unroll 1
    for (int t = 0; t < T_; t++) {
        // prefetch next step's xw (off critical path)
        float xn = 0.f;
        if (t + 1 < T_) xn = __ldg(xp + (size_t)(t + 1) * DH);

        // dot over this thread's K-half: 64 packed FMAs, 8 indep chains
        const ulonglong2* hp = (const ulonglong2*)&sh_h[t & 1][k0];
        unsigned long long a[8];
#pragma unroll
        for (int q = 0; q < 8; q++) a[q] = 0ULL;
#pragma unroll
        for (int i = 0; i < 8; i++) {
            ulonglong2 h0v = hp[4 * i + 0];
            ulonglong2 h1v = hp[4 * i + 1];
            ulonglong2 h2v = hp[4 * i + 2];
            ulonglong2 h3v = hp[4 * i + 3];
            fma2(a[0], wh[8 * i + 0], h0v.x);
            fma2(a[1], wh[8 * i + 1], h0v.y);
            fma2(a[2], wh[8 * i + 2], h1v.x);
            fma2(a[3], wh[8 * i + 3], h1v.y);
            fma2(a[4], wh[8 * i + 4], h2v.x);
            fma2(a[5], wh[8 * i + 5], h2v.y);
            fma2(a[6], wh[8 * i + 6], h3v.x);
            fma2(a[7], wh[8 * i + 7], h3v.y);
        }
        add2(a[0], a[4]); add2(a[1], a[5]); add2(a[2], a[6]); add2(a[3], a[7]);
        add2(a[0], a[2]); add2(a[1], a[3]);
        add2(a[0], a[1]);
        float2 f = up2(a[0]);
        float part = f.x + f.y;
        part += __shfl_xor_sync(0xffffffffu, part, 16);  // combine the two K-halves

        float hnew = tanhf(part + xv);

        const int nxt = (t + 1) & 1;
        if (sub == 0) {
            // final output for this j
            op[(size_t)t * DH] = hnew;
            // local copy for next step
            sh_h[nxt][j] = hnew;
            // remote copy into peer's buffer
            unsigned int ra = rh + (unsigned)((nxt << 8) + j) * 4u;
            asm volatile("st.shared::cluster.b32 [%0], %1;"
                         :: "r"(ra), "r"(__float_as_uint(hnew)) : "memory");
            // CLUSTER-scope release arrive on the peer's barrier:
            // orders the st.shared::cluster above before the phase flip.
            asm volatile("mbarrier.arrive.release.cluster.shared::cluster.b64 _, [%0];"
                         :: "r"(rbar) : "memory");
        }
        __syncthreads();   // local half visible CTA-wide (drains STS)

        // wait for peer's 128 arrivals for this step (acquire, cluster scope)
        {
            unsigned int parity = (unsigned int)(t & 1);
            unsigned int done;
            asm volatile(
                "{\n\t"
                ".reg .pred p;\n\t"
                "mbarrier.try_wait.parity.acquire.cluster.shared::cta.b64 p, [%1], %2;\n\t"
                "selp.b32 %0, 1, 0, p;\n\t"
                "}"
                : "=r"(done) : "r"(lbar), "r"(parity) : "memory");
            if (!done) {
                asm volatile(
                    "{\n\t"
                    ".reg .pred P1;\n\t"
                    "WL_%=:\n\t"
                    "mbarrier.try_wait.parity.acquire.cluster.shared::cta.b64 P1, [%0], %1, 0x989680;\n\t"
                    "@P1 bra.uni WD_%=;\n\t"
                    "bra.uni WL_%=;\n\t"
                    "WD_%=:\n\t"
                    "}"
                    :: "r"(lbar), "r"(parity) : "memory");
            }
        }
        xv = xn;
    }
}

// ============================================================================
extern "C" void kernel_launch(void* const* d_in, const int* in_sizes, int n_in,
                              void* d_out, int out_size)
{
    const float* x    = (const float*)d_in[0];   // (64, 2048, 128)
    const float* h0   = (const float*)d_in[1];   // (64, 256)
    const float* W    = (const float*)d_in[2];   // (256, 384)
    const float* bias = (const float*)d_in[3];   // (256,)
    float* out = (float*)d_out;                  // (64, 2048, 256)

    (void)in_sizes; (void)n_in; (void)out_size;

    gemm_xw_kernel<<<dim3(1024, 4), 256>>>(x, W, bias);
    rnn_scan_kernel<<<128, 256>>>(W, h0, out);
}

// round 16
// speedup vs baseline: 1.1456x; 1.0373x over previous
#include <cuda_runtime.h>
#include <cstdint>

#define B_   64
#define T_   2048
#define DIN  128
#define DH   256
#define WST  384   // W row stride (fan_in = 128 + 256)

// 128MB scratch for xw = x @ Wx^T + b   (sanctioned __device__ scratch)
__device__ float g_xw[33554432];   // 64*2048*256

// ---------- packed f32x2 helpers ----------
__device__ __forceinline__ unsigned long long pk2(float x, float y) {
    unsigned long long r;
    asm("mov.b64 %0, {%1,%2};" : "=l"(r) : "f"(x), "f"(y));
    return r;
}
__device__ __forceinline__ float2 up2(unsigned long long v) {
    float2 r;
    asm("mov.b64 {%0,%1}, %2;" : "=f"(r.x), "=f"(r.y) : "l"(v));
    return r;
}
__device__ __forceinline__ void fma2(unsigned long long& d,
                                     unsigned long long a,
                                     unsigned long long b) {
    asm("fma.rn.f32x2 %0, %1, %2, %3;" : "=l"(d) : "l"(a), "l"(b), "l"(d));
}
__device__ __forceinline__ void add2(unsigned long long& d,
                                     unsigned long long a) {
    asm("add.rn.f32x2 %0, %1, %2;" : "=l"(d) : "l"(d), "l"(a));
}
// fast tanh: 1 - 2/(exp(2x)+1) with approx ex2/rcp (abs err ~2e-7)
__device__ __forceinline__ float fast_tanh(float z) {
    float p = z * 2.8853900817779268f;   // 2*log2(e)
    float e; asm("ex2.approx.f32 %0, %1;" : "=f"(e) : "f"(p));
    float r; asm("rcp.approx.f32 %0, %1;" : "=f"(r) : "f"(e + 1.0f));
    return fmaf(-2.0f, r, 1.0f);
}

// ============================================================================
// Kernel 1: xw[m][n] = sum_k X[m][k] * W[n][k] + bias[n]
// ============================================================================
__global__ __launch_bounds__(256, 1) void gemm_xw_kernel(
    const float* __restrict__ X, const float* __restrict__ W,
    const float* __restrict__ bias)
{
    __shared__ __align__(16) float  Xs[128][64];
    __shared__ __align__(16) float4 Wsv[64][16];

    const int tid = threadIdx.x;
    const int m0 = blockIdx.x * 128;
    const int n0 = blockIdx.y * 64;
    const int tx = tid & 15;
    const int ty = tid >> 4;
    const int row = ty * 8;

    unsigned long long acc[8][4];
#pragma unroll
    for (int i = 0; i < 8; i++)
#pragma unroll
        for (int j = 0; j < 4; j++) acc[i][j] = 0ULL;

    for (int kb = 0; kb < 2; kb++) {
#pragma unroll
        for (int it = 0; it < 8; it++) {
            int v = tid + 256 * it;
            int m = v >> 4;
            int kv = v & 15;
            float4 xv = *(const float4*)(X + (size_t)(m0 + m) * DIN + kb * 64 + kv * 4);
            *(float4*)&Xs[m][kv * 4] = xv;
        }
#pragma unroll
        for (int it = 0; it < 4; it++) {
            int v = tid + 256 * it;
            int n = v >> 4;
            int kv = v & 15;
            float4 wv = *(const float4*)(W + (size_t)(n0 + n) * WST + kb * 64 + kv * 4);
            Wsv[n][kv ^ (n & 7)] = wv;
        }
        __syncthreads();

#pragma unroll
        for (int k4 = 0; k4 < 16; k4++) {
            ulonglong2 bv[4];
#pragma unroll
            for (int j = 0; j < 4; j++) {
                int n = tx + 16 * j;
                bv[j] = *(const ulonglong2*)&Wsv[n][k4 ^ (n & 7)];
            }
#pragma unroll
            for (int i = 0; i < 8; i++) {
                ulonglong2 av = *(const ulonglong2*)&Xs[row + i][k4 * 4];
#pragma unroll
                for (int j = 0; j < 4; j++) {
                    fma2(acc[i][j], av.x, bv[j].x);
                    fma2(acc[i][j], av.y, bv[j].y);
                }
            }
        }
        __syncthreads();
    }

    float bb[4];
#pragma unroll
    for (int j = 0; j < 4; j++) bb[j] = bias[n0 + tx + 16 * j];
#pragma unroll
    for (int i = 0; i < 8; i++) {
#pragma unroll
        for (int j = 0; j < 4; j++) {
            float2 v = up2(acc[i][j]);
            g_xw[(size_t)(m0 + row + i) * DH + n0 + tx + 16 * j] = v.x + v.y + bb[j];
        }
    }
}

// ============================================================================
// Kernel 2: scan, output-split 2-CTA cluster per batch.
//   Thread (j, sub) K-range = [local-origin 64 | peer-origin 64]:
//     local part computed BEFORE the peer wait (hides DSMEM transit),
//     peer part after try_wait(parity (t-1)&1).
//   Exchange: per-lane st.shared::cluster, then ONE plain release-arrive per
//   warp from lane 0 (barrier init count = 8).
//   R12 crash fix: the mid-loop wait leaves step T-1's remote ops
//   unconsumed at exit -> cross-CTA DSMEM ops in flight when a CTA's SMEM
//   is torn down -> ULF. Fix: skip remote push at t==T-1 (no consumer) and
//   add a trailing cluster barrier before exit.
// ============================================================================
__global__ void __cluster_dims__(2, 1, 1) __launch_bounds__(256, 1)
rnn_scan_kernel(const float* __restrict__ W, const float* __restrict__ h0,
                float* __restrict__ out)
{
    __shared__ __align__(16) float sh_h[2][DH];
    __shared__ __align__(8) unsigned long long mbar;

    const int tid  = threadIdx.x;
    const int lane = tid & 31;
    const int warp = tid >> 5;                 // 8 warps
    const int sub  = lane >> 4;                // 64-chunk selector (0/1)
    const int jl   = warp * 16 + (lane & 15);  // output within CTA: 0..127
    const int b    = blockIdx.x >> 1;
    const unsigned int s = (unsigned int)(blockIdx.x & 1);
    const unsigned int peer = s ^ 1u;
    const int j = (int)(s << 7) + jl;          // global output index 0..255
    const int loc_off  = (int)(s    << 7) + (sub << 6);  // local-origin 64 h's
    const int peer_off = (int)(peer << 7) + (sub << 6);  // peer-origin 64 h's

    // weights: 32 f32x2 for the local-origin K chunk, 32 for the peer-origin
    unsigned long long wl[32], wp_[32];
    {
        const float4* p0 = (const float4*)(W + (size_t)j * WST + DIN + loc_off);
        const float4* p1 = (const float4*)(W + (size_t)j * WST + DIN + peer_off);
#pragma unroll
        for (int i = 0; i < 16; i++) {
            float4 v = p0[i];
            wl[2 * i]     = pk2(v.x, v.y);
            wl[2 * i + 1] = pk2(v.z, v.w);
            float4 u = p1[i];
            wp_[2 * i]     = pk2(u.x, u.y);
            wp_[2 * i + 1] = pk2(u.z, u.w);
        }
    }

    // init h state (full 256 locally in both CTAs) + mbarrier (count 8:
    // one plain arrive per peer warp)
    if (tid < DH) sh_h[0][tid] = h0[(size_t)b * DH + tid];
    unsigned int lbar = (unsigned int)__cvta_generic_to_shared(&mbar);
    if (tid == 0) {
        asm volatile("mbarrier.init.shared.b64 [%0], %1;"
                     :: "r"(lbar), "r"(8) : "memory");
    }
    __syncthreads();
    asm volatile("barrier.cluster.arrive.aligned;" ::: "memory");
    asm volatile("barrier.cluster.wait.aligned;"   ::: "memory");

    // peer-CTA addresses
    unsigned int rbar, rh;
    asm("mapa.shared::cluster.u32 %0, %1, %2;" : "=r"(rbar) : "r"(lbar), "r"(peer));
    unsigned int lh = (unsigned int)__cvta_generic_to_shared(&sh_h[0][0]);
    asm("mapa.shared::cluster.u32 %0, %1, %2;" : "=r"(rh) : "r"(lh), "r"(peer));

    const float* xp = g_xw + (size_t)b * T_ * DH + j;
    float*       op = out  + (size_t)b * T_ * DH + j;

    float xv = __ldg(xp);   // prefetch t=0

#pragma unroll 1
    for (int t = 0; t < T_; t++) {
        const int cur = t & 1;
        // prefetch next step's xw (clamped at the end; off critical path)
        float xn = __ldg(xp + (size_t)((t + 1 < T_) ? t + 1 : t) * DH);

        unsigned long long a[8];
#pragma unroll
        for (int q = 0; q < 8; q++) a[q] = 0ULL;

        // ---- local-origin half: ready after last step's __syncthreads ----
        {
            const ulonglong2* hl = (const ulonglong2*)&sh_h[cur][loc_off];
#pragma unroll
            for (int i = 0; i < 4; i++) {
                ulonglong2 h0v = hl[4 * i + 0];
                ulonglong2 h1v = hl[4 * i + 1];
                ulonglong2 h2v = hl[4 * i + 2];
                ulonglong2 h3v = hl[4 * i + 3];
                fma2(a[0], wl[8 * i + 0], h0v.x);
                fma2(a[1], wl[8 * i + 1], h0v.y);
                fma2(a[2], wl[8 * i + 2], h1v.x);
                fma2(a[3], wl[8 * i + 3], h1v.y);
                fma2(a[4], wl[8 * i + 4], h2v.x);
                fma2(a[5], wl[8 * i + 5], h2v.y);
                fma2(a[6], wl[8 * i + 6], h3v.x);
                fma2(a[7], wl[8 * i + 7], h3v.y);
            }
        }

        // ---- wait for peer's previous-step push (skipped at t=0) ----
        if (t != 0) {
            unsigned int parity = (unsigned int)((t - 1) & 1);
            unsigned int done;
            asm volatile(
                "{\n\t"
                ".reg .pred p;\n\t"
                "mbarrier.try_wait.parity.acquire.cluster.shared::cta.b64 p, [%1], %2;\n\t"
                "selp.b32 %0, 1, 0, p;\n\t"
                "}"
                : "=r"(done) : "r"(lbar), "r"(parity) : "memory");
            if (!done) {
                asm volatile(
                    "{\n\t"
                    ".reg .pred P1;\n\t"
                    "WL_%=:\n\t"
                    "mbarrier.try_wait.parity.acquire.cluster.shared::cta.b64 P1, [%0], %1, 0x989680;\n\t"
                    "@P1 bra.uni WD_%=;\n\t"
                    "bra.uni WL_%=;\n\t"
                    "WD_%=:\n\t"
                    "}"
                    :: "r"(lbar), "r"(parity) : "memory");
            }
        }

        // ---- peer-origin half ----
        {
            const ulonglong2* hq = (const ulonglong2*)&sh_h[cur][peer_off];
#pragma unroll
            for (int i = 0; i < 4; i++) {
                ulonglong2 h0v = hq[4 * i + 0];
                ulonglong2 h1v = hq[4 * i + 1];
                ulonglong2 h2v = hq[4 * i + 2];
                ulonglong2 h3v = hq[4 * i + 3];
                fma2(a[0], wp_[8 * i + 0], h0v.x);
                fma2(a[1], wp_[8 * i + 1], h0v.y);
                fma2(a[2], wp_[8 * i + 2], h1v.x);
                fma2(a[3], wp_[8 * i + 3], h1v.y);
                fma2(a[4], wp_[8 * i + 4], h2v.x);
                fma2(a[5], wp_[8 * i + 5], h2v.y);
                fma2(a[6], wp_[8 * i + 6], h3v.x);
                fma2(a[7], wp_[8 * i + 7], h3v.y);
            }
        }

        add2(a[0], a[4]); add2(a[1], a[5]); add2(a[2], a[6]); add2(a[3], a[7]);
        add2(a[0], a[2]); add2(a[1], a[3]);
        add2(a[0], a[1]);
        float2 f = up2(a[0]);
        float part = f.x + f.y;
        part += __shfl_xor_sync(0xffffffffu, part, 16);  // combine 128+128

        float hnew = fast_tanh(part + xv);

        const int nxt = cur ^ 1;
        const bool last = (t + 1 == T_);
        if (sub) {
            op[(size_t)t * DH] = hnew;                    // final output
        } else {
            sh_h[nxt][j] = hnew;                          // local copy
            if (!last) {
                // remote copy into peer's buffer (no consumer at last step)
                unsigned int ra = rh + (unsigned)((nxt << 8) + j) * 4u;
                asm volatile("st.shared::cluster.b32 [%0], %1;"
                             :: "r"(ra), "r"(__float_as_uint(hnew)) : "memory");
            }
        }
        __syncwarp();
        if (lane == 0 && !last) {
            // ONE plain release-arrive per warp (covers the warp's 16 remote
            // stores, ordered by the syncwarp above). Same encoding as R6.
            asm volatile("mbarrier.arrive.release.cluster.shared::cluster.b64 _, [%0];"
                         :: "r"(rbar) : "memory");
        }
        __syncthreads();   // local-half h visible CTA-wide for next step
        xv = xn;
    }

    // Trailing cluster barrier: no CTA exits while any peer-directed DSMEM
    // op could still be in flight (release-ordered by the arrive).
    asm volatile("barrier.cluster.arrive.aligned;" ::: "memory");
    asm volatile("barrier.cluster.wait.aligned;"   ::: "memory");
}

// ============================================================================
extern "C" void kernel_launch(void* const* d_in, const int* in_sizes, int n_in,
                              void* d_out, int out_size)
{
    const float* x    = (const float*)d_in[0];   // (64, 2048, 128)
    const float* h0   = (const float*)d_in[1];   // (64, 256)
    const float* W    = (const float*)d_in[2];   // (256, 384)
    const float* bias = (const float*)d_in[3];   // (256,)
    float* out = (float*)d_out;                  // (64, 2048, 256)

    (void)in_sizes; (void)n_in; (void)out_size;

    gemm_xw_kernel<<<dim3(1024, 4), 256>>>(x, W, bias);
    rnn_scan_kernel<<<128, 256>>>(W, h0, out);
}